// round 17
// baseline (speedup 1.0000x reference)
#include <cuda_runtime.h>
#include <cuda_fp16.h>
#include <cstdint>

// ---------------------------------------------------------------------------
// Problem: B=16, S=1024, IN=512, OUT=256.
// out = softmax((x Wq^T)(x Wk^T)^T / sqrt(512)) (x Wv^T)
// RoPE uses ONE fixed rotation per dim-pair applied identically to Q and K;
// 2x2 rotations are orthogonal => (Rq).(Rk) = q.k, and V is unroped, so RoPE
// cancels exactly and is skipped.
//
// R17: 512 threads/CTA, warp grid 4(M)x4(N), warp tile 32x64. Same 128x256
// CTA tiles and arithmetic as R16 (bit-identical results); occupancy 2x.
// ---------------------------------------------------------------------------
#define BATCH   16
#define SEQ     1024
#define IN_DIM  512
#define OUT_DIM 256

#define THREADS 512
#define BK 16              // K elements per chunk

#define ROWB 48            // SMEM row stride bytes (16 elems*2B = 32B + 16B pad)
#define T128 (128 * ROWB)             // 128-row b16 tile: 6144 B
#define T256 (256 * ROWB)             // 256-row b16 tile: 12288 B
#define STAGE_SC  (2 * T128 + T256)   // A1 A2 B256 : 24576 B
#define STAGE_PV  (T128 + T256)       // A B256 : 18432 B

#define SCALE 0.044194173824159216f   // 1/sqrt(512)

// ---------------------------------------------------------------------------
// Scratch (device globals; allocations are forbidden)
// ---------------------------------------------------------------------------
__device__ __half g_q1 [BATCH * SEQ * OUT_DIM];        // q hi (fp16)
__device__ __half g_q2 [BATCH * SEQ * OUT_DIM];        // q lo (fp16), q1+q2==q
__device__ __half g_kh [BATCH * SEQ * OUT_DIM];        // k (fp16)
__device__ __half g_vth[BATCH * OUT_DIM * SEQ];        // [b][d][s]  (V^T fp16)
__device__ __half g_sh [(size_t)BATCH * SEQ * SEQ];    // scaled scores (fp16)
__device__ float  g_pm [BATCH * SEQ * 4];              // partial row max
__device__ float  g_ps [BATCH * SEQ * 4];              // partial sum-exp
__device__ float  g_m  [BATCH * SEQ];                  // row max
__device__ float  g_inv[BATCH * SEQ];                  // 1 / sum(exp(s - m))

// ---------------------------------------------------------------------------
// Helpers
// ---------------------------------------------------------------------------
__device__ __forceinline__ uint32_t smem_u32(const void* p) {
    uint32_t a;
    asm("{ .reg .u64 t; cvta.to.shared.u64 t, %1; cvt.u32.u64 %0, t; }"
        : "=r"(a) : "l"(p));
    return a;
}

#define LDSM4(R, addr) \
    asm volatile("ldmatrix.sync.aligned.m8n8.x4.shared.b16 {%0,%1,%2,%3}, [%4];" \
        : "=r"((R)[0]), "=r"((R)[1]), "=r"((R)[2]), "=r"((R)[3]) : "r"(addr))

#define MMA16816_F16(C, A, B0, B1) \
    asm volatile( \
        "mma.sync.aligned.m16n8k16.row.col.f32.f16.f16.f32 " \
        "{%0,%1,%2,%3}, {%4,%5,%6,%7}, {%8,%9}, {%0,%1,%2,%3};" \
        : "+f"((C)[0]), "+f"((C)[1]), "+f"((C)[2]), "+f"((C)[3]) \
        : "r"((A)[0]), "r"((A)[1]), "r"((A)[2]), "r"((A)[3]), \
          "r"(B0), "r"(B1))

__device__ __forceinline__ void split_f16(float x, float y,
                                          uint32_t& hi, uint32_t& lo) {
    __half2 h = __floats2half2_rn(x, y);
    float2 q = __half22float2(h);
    __half2 l = __floats2half2_rn(x - q.x, y - q.y);
    hi = *reinterpret_cast<uint32_t*>(&h);
    lo = *reinterpret_cast<uint32_t*>(&l);
}

// ldmatrix addresses: 2 A-tiles (warp tile 32 rows) + 4 B-tiles (64 cols).
struct Addr256 {
    uint32_t a[2];
    uint32_t b[4];
};
__device__ __forceinline__ Addr256 make_addr256(uint32_t sb, uint32_t boff) {
    const int tid  = threadIdx.x;
    const int lane = tid & 31;
    const int warp = tid >> 5;           // 0..15
    const int wm = (warp >> 2) * 32;     // M origin (0,32,64,96)
    const int wn = (warp & 3) * 64;      // N origin (0,64,128,192)
    Addr256 r;
    #pragma unroll
    for (int mi = 0; mi < 2; ++mi)
        r.a[mi] = sb + (uint32_t)((wm + mi * 16 + (lane & 15)) * ROWB
                                  + (lane >> 4) * 16);
    #pragma unroll
    for (int p = 0; p < 4; ++p)
        r.b[p] = sb + boff
               + (uint32_t)((wn + p * 16 + (lane & 7) + ((lane & 16) ? 8 : 0)) * ROWB
                            + ((lane & 8) ? 16 : 0));
    return r;
}

// Fragment coordinate helpers (warp tile 32x64).
__device__ __forceinline__ int frag_row(int mi) {
    int lane = threadIdx.x & 31, warp = threadIdx.x >> 5;
    return (warp >> 2) * 32 + mi * 16 + (lane >> 2);
}
__device__ __forceinline__ int frag_col64(int ni) {
    int lane = threadIdx.x & 31, warp = threadIdx.x >> 5;
    return (warp & 3) * 64 + ni * 8 + 2 * (lane & 3);
}

// ===========================================================================
// qkv mainloop (128x256): A fp32 -> exact fp16 split (a1,a2); B fp32 -> fp16.
// 2-pass MMA.
// ===========================================================================
__device__ __forceinline__ void gemm256_qkv(const float* __restrict__ A,
                                            const float* __restrict__ B,
                                            int nchunks, float (&acc)[2][8][4]) {
    __shared__ __align__(16) char smem[2 * STAGE_SC];   // 48 KB

    const int tid = threadIdx.x;
    const uint32_t sb = smem_u32(smem);
    Addr256 ad = make_addr256(sb, 2u * T128);

    const int r0 = tid >> 2, f0 = tid & 3;   // A row r0; B rows r0, r0+128

    float4 pa, pb0, pb1;

    auto load_pf = [&](int ch) {
        const float* An = A + (size_t)ch * BK;
        const float* Bn = B + (size_t)ch * BK;
        pa  = *reinterpret_cast<const float4*>(An + (size_t)r0 * IN_DIM + f0 * 4);
        pb0 = *reinterpret_cast<const float4*>(Bn + (size_t)r0 * IN_DIM + f0 * 4);
        pb1 = *reinterpret_cast<const float4*>(Bn + (size_t)(r0 + 128) * IN_DIM + f0 * 4);
    };

    auto store_pf = [&](int st) {
        char* base = smem + st * STAGE_SC;
        {
            uint32_t h0, l0, h1, l1;
            split_f16(pa.x, pa.y, h0, l0);
            split_f16(pa.z, pa.w, h1, l1);
            char* dst = base + r0 * ROWB + f0 * 8;
            *reinterpret_cast<uint2*>(dst)        = make_uint2(h0, h1);
            *reinterpret_cast<uint2*>(dst + T128) = make_uint2(l0, l1);
        }
        #pragma unroll
        for (int i = 0; i < 2; ++i) {
            int r = r0 + 128 * i;
            float4 v = i ? pb1 : pb0;
            __half2 h0 = __floats2half2_rn(v.x, v.y);
            __half2 h1 = __floats2half2_rn(v.z, v.w);
            *reinterpret_cast<uint2*>(base + 2 * T128 + r * ROWB + f0 * 8) =
                make_uint2(*reinterpret_cast<uint32_t*>(&h0),
                           *reinterpret_cast<uint32_t*>(&h1));
        }
    };

    load_pf(0);
    store_pf(0);
    if (nchunks > 1) load_pf(1);
    __syncthreads();

    #pragma unroll 1
    for (int ch = 0; ch < nchunks; ++ch) {
        const int st = ch & 1;
        const uint32_t soff = (uint32_t)st * STAGE_SC;

        uint32_t a1[2][4], a2[2][4], bf[8][2];
        #pragma unroll
        for (int mi = 0; mi < 2; ++mi) {
            LDSM4(a1[mi], ad.a[mi] + soff);
            LDSM4(a2[mi], ad.a[mi] + soff + T128);
        }
        #pragma unroll
        for (int p = 0; p < 4; ++p) {
            uint32_t t[4];
            LDSM4(t, ad.b[p] + soff);
            bf[2*p][0] = t[0]; bf[2*p][1] = t[1];
            bf[2*p+1][0] = t[2]; bf[2*p+1][1] = t[3];
        }

        if (ch + 1 < nchunks) store_pf(st ^ 1);
        if (ch + 2 < nchunks) load_pf(ch + 2);

        #pragma unroll
        for (int mi = 0; mi < 2; ++mi)
            #pragma unroll
            for (int ni = 0; ni < 8; ++ni) {
                MMA16816_F16(acc[mi][ni], a1[mi], bf[ni][0], bf[ni][1]);
                MMA16816_F16(acc[mi][ni], a2[mi], bf[ni][0], bf[ni][1]);
            }

        __syncthreads();
    }
}

// ===========================================================================
// scores mainloop: acc += (A1+A2)[128xK] @ B[256xK]^T, all fp16 raw.
// smem passed in so the kernel can reuse it for the stats epilogue.
// ===========================================================================
__device__ __forceinline__ void gemm256_split(const __half* __restrict__ A1,
                                              const __half* __restrict__ A2,
                                              const __half* __restrict__ B,
                                              int lda, int ldb, int nchunks,
                                              float (&acc)[2][8][4],
                                              char* smem) {
    const int tid = threadIdx.x;
    const uint32_t sb = smem_u32(smem);
    Addr256 ad = make_addr256(sb, 2u * T128);

    const int ra = tid >> 2, sa = tid & 3;   // A: 8B segs
    const int rb = tid >> 1, sb2 = tid & 1;  // B: 16B segs

    uint2 p1, p2;
    uint4 pb;

    auto load_pf = [&](int ch) {
        p1 = *reinterpret_cast<const uint2*>(A1 + (size_t)ch * BK + (size_t)ra * lda + sa * 4);
        p2 = *reinterpret_cast<const uint2*>(A2 + (size_t)ch * BK + (size_t)ra * lda + sa * 4);
        pb = *reinterpret_cast<const uint4*>(B  + (size_t)ch * BK + (size_t)rb * ldb + sb2 * 8);
    };

    auto store_pf = [&](int st) {
        char* base = smem + st * STAGE_SC;
        uint32_t offa = ra * ROWB + sa * 8;
        *reinterpret_cast<uint2*>(base + offa)        = p1;
        *reinterpret_cast<uint2*>(base + T128 + offa) = p2;
        *reinterpret_cast<uint4*>(base + 2 * T128 + rb * ROWB + sb2 * 16) = pb;
    };

    load_pf(0);
    store_pf(0);
    if (nchunks > 1) load_pf(1);
    __syncthreads();

    #pragma unroll 1
    for (int ch = 0; ch < nchunks; ++ch) {
        const int st = ch & 1;
        const uint32_t soff = (uint32_t)st * STAGE_SC;

        uint32_t a1[2][4], a2[2][4], bf[8][2];
        #pragma unroll
        for (int mi = 0; mi < 2; ++mi) {
            LDSM4(a1[mi], ad.a[mi] + soff);
            LDSM4(a2[mi], ad.a[mi] + soff + T128);
        }
        #pragma unroll
        for (int p = 0; p < 4; ++p) {
            uint32_t t[4];
            LDSM4(t, ad.b[p] + soff);
            bf[2*p][0] = t[0]; bf[2*p][1] = t[1];
            bf[2*p+1][0] = t[2]; bf[2*p+1][1] = t[3];
        }

        if (ch + 1 < nchunks) store_pf(st ^ 1);
        if (ch + 2 < nchunks) load_pf(ch + 2);

        #pragma unroll
        for (int mi = 0; mi < 2; ++mi)
            #pragma unroll
            for (int ni = 0; ni < 8; ++ni) {
                MMA16816_F16(acc[mi][ni], a1[mi], bf[ni][0], bf[ni][1]);
                MMA16816_F16(acc[mi][ni], a2[mi], bf[ni][0], bf[ni][1]);
            }

        __syncthreads();
    }
}

// ===========================================================================
// pv mainloop: acc += P[128xK] @ B[256xK]^T ; P = exp(A - m)*inv on the fly.
// ===========================================================================
__device__ __forceinline__ void gemm256_pv(const __half* __restrict__ A,
                                           const __half* __restrict__ B,
                                           int lda, int ldb, int nchunks,
                                           float (&acc)[2][8][4],
                                           float mrow, float irow) {
    __shared__ __align__(16) char smem[2 * STAGE_PV];   // 36 KB

    const int tid = threadIdx.x;
    const uint32_t sb = smem_u32(smem);
    Addr256 ad = make_addr256(sb, (uint32_t)T128);

    const int ra = tid >> 2, sa = tid & 3;   // A: 8B segs, row 0..127
    const int rb = tid >> 1, sb2 = tid & 1;  // B: 16B segs, row 0..255

    uint2 pa;
    uint4 pb;

    auto load_pf = [&](int ch) {
        pa = *reinterpret_cast<const uint2*>(A + (size_t)ch * BK + (size_t)ra * lda + sa * 4);
        pb = *reinterpret_cast<const uint4*>(B + (size_t)ch * BK + (size_t)rb * ldb + sb2 * 8);
    };

    auto store_pf = [&](int st) {
        char* base = smem + st * STAGE_PV;
        uint32_t w[2] = {pa.x, pa.y};
        #pragma unroll
        for (int j = 0; j < 2; ++j) {
            __half2 h = *reinterpret_cast<__half2*>(&w[j]);
            float2 f = __half22float2(h);
            f.x = __expf(f.x - mrow) * irow;
            f.y = __expf(f.y - mrow) * irow;
            __half2 o = __floats2half2_rn(f.x, f.y);
            w[j] = *reinterpret_cast<uint32_t*>(&o);
        }
        *reinterpret_cast<uint2*>(base + ra * ROWB + sa * 8) = make_uint2(w[0], w[1]);
        *reinterpret_cast<uint4*>(base + T128 + rb * ROWB + sb2 * 16) = pb;
    };

    load_pf(0);
    store_pf(0);
    if (nchunks > 1) load_pf(1);
    __syncthreads();

    #pragma unroll 1
    for (int ch = 0; ch < nchunks; ++ch) {
        const int st = ch & 1;
        const uint32_t soff = (uint32_t)st * STAGE_PV;

        uint32_t ah[2][4], bf[8][2];
        #pragma unroll
        for (int mi = 0; mi < 2; ++mi)
            LDSM4(ah[mi], ad.a[mi] + soff);
        #pragma unroll
        for (int p = 0; p < 4; ++p) {
            uint32_t t[4];
            LDSM4(t, ad.b[p] + soff);
            bf[2*p][0] = t[0]; bf[2*p][1] = t[1];
            bf[2*p+1][0] = t[2]; bf[2*p+1][1] = t[3];
        }

        if (ch + 1 < nchunks) store_pf(st ^ 1);
        if (ch + 2 < nchunks) load_pf(ch + 2);

        #pragma unroll
        for (int mi = 0; mi < 2; ++mi)
            #pragma unroll
            for (int ni = 0; ni < 8; ++ni)
                MMA16816_F16(acc[mi][ni], ah[mi], bf[ni][0], bf[ni][1]);

        __syncthreads();
    }
}

// ---------------------------------------------------------------------------
// Kernel 1: fused QKV, full OUT_DIM per CTA. grid (128 mt, 3 which).
// ---------------------------------------------------------------------------
__global__ void __launch_bounds__(THREADS, 1)
qkv_kernel(const float* __restrict__ x,
           const float* __restrict__ wq, const float* __restrict__ bq,
           const float* __restrict__ wk, const float* __restrict__ bk,
           const float* __restrict__ wv, const float* __restrict__ bv) {
    const int mt = blockIdx.x, which = blockIdx.y;
    const float* w    = (which == 0) ? wq : (which == 1) ? wk : wv;
    const float* bias = (which == 0) ? bq : (which == 1) ? bk : bv;

    float acc[2][8][4];
    #pragma unroll
    for (int i = 0; i < 2; ++i)
        #pragma unroll
        for (int j = 0; j < 8; ++j)
            #pragma unroll
            for (int r = 0; r < 4; ++r) acc[i][j][r] = 0.f;

    gemm256_qkv(x + (size_t)mt * 128 * IN_DIM, w, IN_DIM / BK, acc);

    #pragma unroll
    for (int mi = 0; mi < 2; ++mi)
        #pragma unroll
        for (int ni = 0; ni < 8; ++ni) {
            int m0 = mt * 128 + frag_row(mi);
            int n  = frag_col64(ni);
            float b0 = __ldg(bias + n), b1 = __ldg(bias + n + 1);
            #pragma unroll
            for (int rr = 0; rr < 2; ++rr) {
                int m = m0 + rr * 8;
                float v0 = acc[mi][ni][2*rr]     + b0;
                float v1 = acc[mi][ni][2*rr + 1] + b1;
                if (which == 2) {
                    int b = m >> 10, s = m & 1023;
                    g_vth[((size_t)b * OUT_DIM + n)     * SEQ + s] = __float2half(v0);
                    g_vth[((size_t)b * OUT_DIM + n + 1) * SEQ + s] = __float2half(v1);
                } else if (which == 1) {
                    __half2 h = __floats2half2_rn(v0, v1);
                    *reinterpret_cast<__half2*>(&g_kh[(size_t)m * OUT_DIM + n]) = h;
                } else {
                    uint32_t hi, lo;
                    split_f16(v0, v1, hi, lo);
                    *reinterpret_cast<uint32_t*>(&g_q1[(size_t)m * OUT_DIM + n]) = hi;
                    *reinterpret_cast<uint32_t*>(&g_q2[(size_t)m * OUT_DIM + n]) = lo;
                }
            }
        }
}

// ---------------------------------------------------------------------------
// Kernel 2: scores = (Q K^T)*SCALE (fp16) + per-CTA row-stat partials.
// grid (8 mt, 4 nt, 16 b).
// ---------------------------------------------------------------------------
__global__ void __launch_bounds__(THREADS, 1)
scores_kernel() {
    __shared__ __align__(16) char smem[2 * STAGE_SC];   // 48 KB (reused below)

    const int mt = blockIdx.x, nt = blockIdx.y, b = blockIdx.z;
    float acc[2][8][4];
    #pragma unroll
    for (int i = 0; i < 2; ++i)
        #pragma unroll
        for (int j = 0; j < 8; ++j)
            #pragma unroll
            for (int r = 0; r < 4; ++r) acc[i][j][r] = 0.f;

    const size_t arow = ((size_t)b * SEQ + mt * 128) * OUT_DIM;
    const size_t brow = ((size_t)b * SEQ + nt * 256) * OUT_DIM;
    gemm256_split(g_q1 + arow, g_q2 + arow, g_kh + brow,
                  OUT_DIM, OUT_DIM, OUT_DIM / BK, acc, smem);

    const int tid  = threadIdx.x;
    const int lane = tid & 31;
    const int warp = tid >> 5;
    const int wn   = warp & 3;

    // Write fp16 scores; overwrite acc with the fp16-roundtripped values so
    // stats match exactly what pv will exp().
    #pragma unroll
    for (int mi = 0; mi < 2; ++mi)
        #pragma unroll
        for (int ni = 0; ni < 8; ++ni) {
            int m0 = mt * 128 + frag_row(mi);
            int n  = nt * 256 + frag_col64(ni);
            __half* base = g_sh + (size_t)b * SEQ * SEQ;
            __half2 v0 = __floats2half2_rn(acc[mi][ni][0] * SCALE,
                                           acc[mi][ni][1] * SCALE);
            __half2 v1 = __floats2half2_rn(acc[mi][ni][2] * SCALE,
                                           acc[mi][ni][3] * SCALE);
            *reinterpret_cast<__half2*>(&base[(size_t)m0 * SEQ + n])       = v0;
            *reinterpret_cast<__half2*>(&base[(size_t)(m0 + 8) * SEQ + n]) = v1;
            float2 r0 = __half22float2(v0);
            float2 r1 = __half22float2(v1);
            acc[mi][ni][0] = r0.x; acc[mi][ni][1] = r0.y;
            acc[mi][ni][2] = r1.x; acc[mi][ni][3] = r1.y;
        }

    // Stats scratch reuses the (dead) mainloop smem.
    float* s_max = reinterpret_cast<float*>(smem);         // [128][4]
    float* s_sum = s_max + 128 * 4;                        // [128][4]

    // Phase A: per-row max over this CTA's 256 columns.
    #pragma unroll
    for (int mi = 0; mi < 2; ++mi)
        #pragma unroll
        for (int rr = 0; rr < 2; ++rr) {
            float vm = -1e30f;
            #pragma unroll
            for (int ni = 0; ni < 8; ++ni)
                vm = fmaxf(vm, fmaxf(acc[mi][ni][2*rr], acc[mi][ni][2*rr+1]));
            vm = fmaxf(vm, __shfl_xor_sync(0xFFFFFFFFu, vm, 1));
            vm = fmaxf(vm, __shfl_xor_sync(0xFFFFFFFFu, vm, 2));
            int row = (warp >> 2) * 32 + mi * 16 + (lane >> 2) + rr * 8;
            if ((lane & 3) == 0) s_max[row * 4 + wn] = vm;
        }
    __syncthreads();

    // Phase B: per-row sum of exp(v - ctamax).
    #pragma unroll
    for (int mi = 0; mi < 2; ++mi)
        #pragma unroll
        for (int rr = 0; rr < 2; ++rr) {
            int row = (warp >> 2) * 32 + mi * 16 + (lane >> 2) + rr * 8;
            float rm = fmaxf(fmaxf(s_max[row*4+0], s_max[row*4+1]),
                             fmaxf(s_max[row*4+2], s_max[row*4+3]));
            float sum = 0.f;
            #pragma unroll
            for (int ni = 0; ni < 8; ++ni)
                sum += __expf(acc[mi][ni][2*rr]   - rm)
                     + __expf(acc[mi][ni][2*rr+1] - rm);
            sum += __shfl_xor_sync(0xFFFFFFFFu, sum, 1);
            sum += __shfl_xor_sync(0xFFFFFFFFu, sum, 2);
            if ((lane & 3) == 0) s_sum[row * 4 + wn] = sum;
        }
    __syncthreads();

    if (tid < 128) {
        int row = tid;
        float rm = fmaxf(fmaxf(s_max[row*4+0], s_max[row*4+1]),
                         fmaxf(s_max[row*4+2], s_max[row*4+3]));
        float sm = s_sum[row*4+0] + s_sum[row*4+1]
                 + s_sum[row*4+2] + s_sum[row*4+3];
        size_t gr = (size_t)b * SEQ + mt * 128 + row;
        g_pm[gr * 4 + nt] = rm;
        g_ps[gr * 4 + nt] = sm;
    }
}

// ---------------------------------------------------------------------------
// Kernel 3: combine 4 partials per row -> g_m, g_inv.
// ---------------------------------------------------------------------------
__global__ void __launch_bounds__(256)
reduce_kernel() {
    int row = blockIdx.x * 256 + threadIdx.x;
    float m0 = g_pm[row*4+0], m1 = g_pm[row*4+1];
    float m2 = g_pm[row*4+2], m3 = g_pm[row*4+3];
    float m = fmaxf(fmaxf(m0, m1), fmaxf(m2, m3));
    float s = g_ps[row*4+0] * __expf(m0 - m)
            + g_ps[row*4+1] * __expf(m1 - m)
            + g_ps[row*4+2] * __expf(m2 - m)
            + g_ps[row*4+3] * __expf(m3 - m);
    g_m[row]   = m;
    g_inv[row] = 1.0f / s;
}

// ---------------------------------------------------------------------------
// Kernel 4: out = softmax(S) @ V. grid (8 mt, 16 b).
// ---------------------------------------------------------------------------
__global__ void __launch_bounds__(THREADS, 1)
pv_kernel(float* __restrict__ out) {
    const int mt = blockIdx.x, b = blockIdx.y;
    float acc[2][8][4];
    #pragma unroll
    for (int i = 0; i < 2; ++i)
        #pragma unroll
        for (int j = 0; j < 8; ++j)
            #pragma unroll
            for (int r = 0; r < 4; ++r) acc[i][j][r] = 0.f;

    const int tid = threadIdx.x;
    const size_t rowbase = (size_t)b * SEQ + mt * 128;
    const float mrow = g_m  [rowbase + (tid >> 2)];
    const float irow = g_inv[rowbase + (tid >> 2)];

    gemm256_pv(g_sh  + ((size_t)b * SEQ + mt * 128) * SEQ,
               g_vth + (size_t)b * OUT_DIM * SEQ,
               SEQ, SEQ, SEQ / BK, acc, mrow, irow);

    #pragma unroll
    for (int mi = 0; mi < 2; ++mi)
        #pragma unroll
        for (int ni = 0; ni < 8; ++ni) {
            int m0r = mt * 128 + frag_row(mi);
            int n   = frag_col64(ni);
            float* base = out + (size_t)b * SEQ * OUT_DIM;
            float2 v0 = make_float2(acc[mi][ni][0], acc[mi][ni][1]);
            float2 v1 = make_float2(acc[mi][ni][2], acc[mi][ni][3]);
            *reinterpret_cast<float2*>(&base[(size_t)m0r * OUT_DIM + n])       = v0;
            *reinterpret_cast<float2*>(&base[(size_t)(m0r + 8) * OUT_DIM + n]) = v1;
        }
}

// ---------------------------------------------------------------------------
// Launcher
// ---------------------------------------------------------------------------
extern "C" void kernel_launch(void* const* d_in, const int* in_sizes, int n_in,
                              void* d_out, int out_size) {
    (void)in_sizes; (void)n_in; (void)out_size;
    const float* x  = (const float*)d_in[0];
    const float* wq = (const float*)d_in[1];
    const float* bq = (const float*)d_in[2];
    const float* wk = (const float*)d_in[3];
    const float* bk = (const float*)d_in[4];
    const float* wv = (const float*)d_in[5];
    const float* bv = (const float*)d_in[6];
    float* out = (float*)d_out;

    qkv_kernel<<<dim3(128, 3), THREADS>>>(x, wq, bq, wk, bk, wv, bv);
    scores_kernel<<<dim3(8, 4, 16), THREADS>>>();
    reduce_kernel<<<BATCH * SEQ / 256, 256>>>();
    pv_kernel<<<dim3(8, 16), THREADS>>>(out);
}